// round 16
// baseline (speedup 1.0000x reference)
#include <cuda_runtime.h>
#include <cuda_bf16.h>
#include <cuda_fp16.h>
#include <cstdint>
#include <cstddef>

#define NM 100000           // movies
#define NU 50000            // users
#define NN 150000           // total nodes
#define NE 500000           // edges
#define D1 128              // emb dim
#define D2 256              // hidden dim

// ---------------- scratch (device globals; no allocation allowed) ----------
__device__ int g_deg[NN];          // zero-init at load; scan1 re-zeroes per run
__device__ int g_off[NN + 1];
__device__ int g_pos[NN];
__device__ int g_srcs[NE];
__device__ int g_eids[NE];
__device__ int g_bsum[256];
__device__ int g_is64;
// fp16 operands
__device__ __align__(256) __half g_xf[(size_t)NN * 128];     // embeddings fp16
__device__ __align__(256) __half g_a1f[(size_t)NN * 128];    // layer-1 aggregate
__device__ __align__(256) __half g_B1f[256 * 256];           // [Wl1;Wr1] k-major
__device__ __align__(256) __half g_B2f[256 * 256];           // [Wl2|Wr2] n-concat
__device__ __align__(256) __half g_pf[(size_t)NN * 128];     // p = h@Wl2 (fp16)
__device__ __align__(256) __half g_qf[(size_t)NN * 128];     // q = h@Wr2+b2 (fp16)
__device__ __align__(256) __half g_rf[(size_t)NN * 128];     // refined fp16 shadow

// ---------------- helpers ----------------------------------------------------
__device__ __forceinline__ int edge_idx(const void* ei, int which, int e) {
    if (g_is64) {
        const long long* p = (const long long*)ei;
        return (int)p[(size_t)which * NE + e];
    } else {
        const int* p = (const int*)ei;
        return p[(size_t)which * NE + e];
    }
}
__device__ __forceinline__ uint32_t pkh(float a, float b) {
    __half2 p = __floats2half2_rn(a, b);
    return *(uint32_t*)&p;
}
__device__ __forceinline__ void cpa16(uint32_t dst, const void* src) {
    asm volatile("cp.async.cg.shared.global [%0], [%1], 16;" :: "r"(dst), "l"(src));
}
__device__ __forceinline__ void cpa_commit() {
    asm volatile("cp.async.commit_group;" ::: "memory");
}
template <int N>
__device__ __forceinline__ void cpa_wait() {
    asm volatile("cp.async.wait_group %0;" :: "n"(N) : "memory");
}
__device__ __forceinline__ void ldsm4(uint32_t* r, uint32_t a) {
    asm volatile("ldmatrix.sync.aligned.m8n8.x4.shared.b16 {%0,%1,%2,%3}, [%4];"
                 : "=r"(r[0]), "=r"(r[1]), "=r"(r[2]), "=r"(r[3]) : "r"(a));
}
__device__ __forceinline__ void ldsm2t(uint32_t* r, uint32_t a) {
    asm volatile("ldmatrix.sync.aligned.m8n8.x2.trans.shared.b16 {%0,%1}, [%2];"
                 : "=r"(r[0]), "=r"(r[1]) : "r"(a));
}
__device__ __forceinline__ void mma_f16(float* c, const uint32_t* a, const uint32_t* b) {
    asm volatile(
        "mma.sync.aligned.m16n8k16.row.col.f32.f16.f16.f32 "
        "{%0,%1,%2,%3},{%4,%5,%6,%7},{%8,%9},{%0,%1,%2,%3};"
        : "+f"(c[0]), "+f"(c[1]), "+f"(c[2]), "+f"(c[3])
        : "r"(a[0]), "r"(a[1]), "r"(a[2]), "r"(a[3]), "r"(b[0]), "r"(b[1]));
}
__device__ __forceinline__ void acc8(float* a, uint4 v) {
    const uint32_t* vp = (const uint32_t*)&v;
#pragma unroll
    for (int i = 0; i < 4; i++) {
        float2 f = __half22float2(*(const __half2*)&vp[i]);
        a[2 * i]     += f.x;
        a[2 * i + 1] += f.y;
    }
}

// ---- fused prep: detect + degree count + split weights + split x ------------
// g_deg is all-zero on entry (load-time init; scan1 re-zeroes each run), so
// counting fuses here. Counting threads self-detect int64 from the first 4
// words (one broadcast cacheline) to avoid racing on g_is64.
__global__ void k_prep(const void* ei,
                       const float* __restrict__ movie, const float* __restrict__ user,
                       const float* __restrict__ Wl1, const float* __restrict__ Wr1,
                       const float* __restrict__ Wl2, const float* __restrict__ Wr2)
{
    int gid = blockIdx.x * 256 + threadIdx.x;
    if (blockIdx.x == 0) {
        const long long* p = (const long long*)ei;
        int bad = 0;
        for (int i = threadIdx.x; i < 2048; i += 256) {
            long long v = p[i];
            if (v < 0 || v >= NN) bad = 1;
        }
        bad = __syncthreads_or(bad);
        if (threadIdx.x == 0) g_is64 = bad ? 0 : 1;
    }
    // degree count (local is64 detection; first 32B broadcast from L1)
    if (gid < NE) {
        const long long* p64 = (const long long*)ei;
        long long a0 = p64[0], a1 = p64[1], a2 = p64[2], a3 = p64[3];
        bool is64 = (a0 >= 0 && a0 < NN) && (a1 >= 0 && a1 < NN) &&
                    (a2 >= 0 && a2 < NN) && (a3 >= 0 && a3 < NN);
        int d = is64 ? (int)p64[(size_t)NE + gid]
                     : ((const int*)ei)[(size_t)NE + gid];
        atomicAdd(&g_deg[d], 1);
    }
    if (gid < 65536) {                       // B1 [k=256][n=256] = [Wl1;Wr1]
        float v = (gid < 32768) ? Wl1[gid] : Wr1[gid - 32768];
        g_B1f[gid] = __float2half(v);
    } else if (gid < 131072) {               // B2 [k=256][n=256] = [Wl2|Wr2]
        int j = gid - 65536;
        int k = j >> 8, n = j & 255;
        float v = (n < 128) ? Wl2[(size_t)k * 128 + n]
                            : Wr2[(size_t)k * 128 + (n - 128)];
        g_B2f[j] = __float2half(v);
    }
    // x split: 8 floats -> 8 fp16 per thread (16B store)
    size_t i = (size_t)gid * 8;
    if (i < (size_t)NN * 128) {
        int row = (int)(i >> 7), col = (int)(i & 127);
        const float* src = (row < NM) ? movie + (size_t)row * 128 + col
                                      : user + (size_t)(row - NM) * 128 + col;
        float4 v0 = *(const float4*)src;
        float4 v1 = *(const float4*)(src + 4);
        uint4 u;
        u.x = pkh(v0.x, v0.y);
        u.y = pkh(v0.z, v0.w);
        u.z = pkh(v1.x, v1.y);
        u.w = pkh(v1.z, v1.w);
        *(uint4*)(g_xf + i) = u;
    }
}

// ---------------- CSR construction -------------------------------------------
// scan1: shuffle-based block scan; consumes g_deg and re-zeroes it.
__global__ void k_scan1() {
    __shared__ int wsum[32];
    int i = blockIdx.x * 1024 + threadIdx.x;
    int v = (i < NN) ? g_deg[i] : 0;
    if (i < NN) g_deg[i] = 0;                 // restore invariant for next run
    int lane = threadIdx.x & 31, w = threadIdx.x >> 5;
    int x = v;
#pragma unroll
    for (int o = 1; o < 32; o <<= 1) {
        int t = __shfl_up_sync(0xFFFFFFFFu, x, o);
        if (lane >= o) x += t;
    }
    if (lane == 31) wsum[w] = x;
    __syncthreads();
    if (w == 0) {
        int s = wsum[lane];
#pragma unroll
        for (int o = 1; o < 32; o <<= 1) {
            int t = __shfl_up_sync(0xFFFFFFFFu, s, o);
            if (lane >= o) s += t;
        }
        wsum[lane] = s;
    }
    __syncthreads();
    int incl = x + ((w > 0) ? wsum[w - 1] : 0);
    if (i < NN) g_off[i] = incl - v;          // exclusive
    if (threadIdx.x == 1023) g_bsum[blockIdx.x] = incl;
}

__global__ void k_scan2() {
    __shared__ int s[256];
    const int NB = (NN + 1023) / 1024;
    int v = (threadIdx.x < NB) ? g_bsum[threadIdx.x] : 0;
    s[threadIdx.x] = v;
    __syncthreads();
#pragma unroll
    for (int off = 1; off < 256; off <<= 1) {
        int t = (threadIdx.x >= off) ? s[threadIdx.x - off] : 0;
        __syncthreads();
        s[threadIdx.x] += t;
        __syncthreads();
    }
    if (threadIdx.x < NB) g_bsum[threadIdx.x] = s[threadIdx.x] - v;
}

__global__ void k_scan3() {
    int i = blockIdx.x * blockDim.x + threadIdx.x;
    if (i < NN) {
        int val = g_off[i] + g_bsum[i >> 10];
        g_off[i] = val;
        g_pos[i] = val;
    }
    if (i == 0) g_off[NN] = NE;
}

__global__ void k_bucket(const void* ei) {
    int e = blockIdx.x * blockDim.x + threadIdx.x;
    if (e < NE) {
        int d = edge_idx(ei, 1, e);
        int p = atomicAdd(&g_pos[d], 1);
        g_srcs[p] = edge_idx(ei, 0, e);
        g_eids[p] = e;
    }
}

// ---------------- layer-1 aggregation (half-warp per node, MLP=2) -----------
__global__ void k_agg1() {
    int hw = threadIdx.x >> 4;
    int lane = threadIdx.x & 15;
    int node = blockIdx.x * 16 + hw;
    if (node >= NN) return;
    int beg = g_off[node], end = g_off[node + 1];
    float a[8];
#pragma unroll
    for (int i = 0; i < 8; i++) a[i] = 0.f;
    int e = beg;
    for (; e + 1 < end; e += 2) {
        int s0 = g_srcs[e], s1 = g_srcs[e + 1];
        uint4 v0 = ((const uint4*)(g_xf + (size_t)s0 * 128))[lane];
        uint4 v1 = ((const uint4*)(g_xf + (size_t)s1 * 128))[lane];
        acc8(a, v0);
        acc8(a, v1);
    }
    if (e < end) {
        uint4 v = ((const uint4*)(g_xf + (size_t)g_srcs[e] * 128))[lane];
        acc8(a, v);
    }
    int cnt = end - beg;
    float inv = 1.0f / (float)(cnt > 0 ? cnt : 1);
    uint4 u;
    u.x = pkh(a[0] * inv, a[1] * inv);
    u.y = pkh(a[2] * inv, a[3] * inv);
    u.z = pkh(a[4] * inv, a[5] * inv);
    u.w = pkh(a[6] * inv, a[7] * inv);
    ((uint4*)(g_a1f + (size_t)node * 128))[lane] = u;
}

// ---------------- fused dual GEMM (BM=128, 512 thr, 1 CTA/SM) ----------------
// Phase A: h = relu([a1|x]@B1 + b1)   -> h tile in smem (swizzled, 64KB)
// Phase B: [p|q] = h@B2 (+b2 on q)    -> g_pf, g_qf fp16
// 16 warps (4m x 4n), warp tile 32x64, BK=32 double-buffered.
// smem: [0,20480) A stages | [20480,53248) B stages | [53248,118784) h
__global__ void __launch_bounds__(512, 1) k_gemm_fused(
    const float* __restrict__ b1, const float* __restrict__ b2)
{
    constexpr int ASTG = 10240;          // 128 rows x 80B
    constexpr int BSTG = 16384;          // 32 rows x 512B
    constexpr uint32_t BOFF = 20480;
    constexpr uint32_t HOFF = 53248;

    extern __shared__ char smr[];
    uint32_t sm0 = (uint32_t)__cvta_generic_to_shared(smr);
    uint32_t hs  = sm0 + HOFF;

    int tid = threadIdx.x, lane = tid & 31, warp = tid >> 5;
    int wm0 = (warp >> 2) * 32, wn0 = (warp & 3) * 64;
    int row0 = blockIdx.x * 128;

    float acc[2][8][4];
#pragma unroll
    for (int i = 0; i < 2; i++)
#pragma unroll
        for (int j = 0; j < 8; j++)
#pragma unroll
            for (int q = 0; q < 4; q++) acc[i][j][q] = 0.f;

    // ---------------- phase A ----------------
    auto stageA = [&](int ch, int s) {
        {
            int row = tid >> 2, c = tid & 3;
            int grow = row0 + row;
            if (grow >= NN) grow = 0;
            int kk = ch * 32 + c * 8;
            const __half* src = (kk < 128)
                ? g_a1f + (size_t)grow * 128 + kk
                : g_xf  + (size_t)grow * 128 + (kk - 128);
            cpa16(sm0 + (uint32_t)(s * ASTG + row * 80 + c * 16), src);
        }
#pragma unroll
        for (int i = 0; i < 2; i++) {
            int idx = tid + i * 512;
            int k = idx >> 5, c = idx & 31;
            const __half* src = g_B1f + (size_t)(ch * 32 + k) * 256 + c * 8;
            cpa16(sm0 + BOFF + (uint32_t)(s * BSTG + k * 512 + ((c ^ (k & 7)) << 4)), src);
        }
    };

    stageA(0, 0);
    cpa_commit();
    for (int ch = 0; ch < 8; ch++) {
        int s = ch & 1;
        if (ch + 1 < 8) {
            stageA(ch + 1, (ch + 1) & 1);
            cpa_commit();
            cpa_wait<1>();
        } else {
            cpa_wait<0>();
        }
        __syncthreads();
        uint32_t ab = sm0 + (uint32_t)(s * ASTG);
        uint32_t bb = sm0 + BOFF + (uint32_t)(s * BSTG);
#pragma unroll
        for (int ks = 0; ks < 2; ks++) {
            uint32_t aF[2][4];
#pragma unroll
            for (int mt = 0; mt < 2; mt++) {
                int r  = wm0 + mt * 16 + (lane & 15);
                int kc = ks * 16 + ((lane >> 4) << 3);
                ldsm4(aF[mt], ab + (uint32_t)(r * 80 + kc * 2));
            }
#pragma unroll
            for (int nt = 0; nt < 8; nt++) {
                int kk = ks * 16 + (lane & 15);
                int cc = (wn0 + nt * 8) >> 3;
                uint32_t bF[2];
                ldsm2t(bF, bb + (uint32_t)(kk * 512 + ((cc ^ (kk & 7)) << 4)));
#pragma unroll
                for (int mt = 0; mt < 2; mt++)
                    mma_f16(acc[mt][nt], aF[mt], bF);
            }
        }
        __syncthreads();
    }

    // phase A epilogue: bias + relu -> h smem (swizzled, 512B row stride)
#pragma unroll
    for (int mt = 0; mt < 2; mt++) {
        int rl = wm0 + mt * 16 + (lane >> 2);
#pragma unroll
        for (int nt = 0; nt < 8; nt++) {
            int col = wn0 + nt * 8 + (lane & 3) * 2;
            float c0 = b1[col], c1 = b1[col + 1];
#pragma unroll
            for (int half = 0; half < 2; half++) {
                int rr = rl + half * 8;
                float vx = fmaxf(acc[mt][nt][half * 2]     + c0, 0.f);
                float vy = fmaxf(acc[mt][nt][half * 2 + 1] + c1, 0.f);
                uint32_t addr = hs + (uint32_t)(rr * 512 +
                    (((col >> 3) ^ (rr & 7)) << 4) + (col & 7) * 2);
                asm volatile("st.shared.b32 [%0], %1;" :: "r"(addr), "r"(pkh(vx, vy)) : "memory");
            }
        }
    }
#pragma unroll
    for (int i = 0; i < 2; i++)
#pragma unroll
        for (int j = 0; j < 8; j++)
#pragma unroll
            for (int q = 0; q < 4; q++) acc[i][j][q] = 0.f;
    __syncthreads();

    // ---------------- phase B: [p|q] = h @ B2 ----------------
    auto stageB = [&](int ch, int s) {
#pragma unroll
        for (int i = 0; i < 2; i++) {
            int idx = tid + i * 512;
            int k = idx >> 5, c = idx & 31;
            const __half* src = g_B2f + (size_t)(ch * 32 + k) * 256 + c * 8;
            cpa16(sm0 + BOFF + (uint32_t)(s * BSTG + k * 512 + ((c ^ (k & 7)) << 4)), src);
        }
    };

    stageB(0, 0);
    cpa_commit();
    for (int ch = 0; ch < 8; ch++) {
        int s = ch & 1;
        if (ch + 1 < 8) {
            stageB(ch + 1, (ch + 1) & 1);
            cpa_commit();
            cpa_wait<1>();
        } else {
            cpa_wait<0>();
        }
        __syncthreads();
        uint32_t bb = sm0 + BOFF + (uint32_t)(s * BSTG);
#pragma unroll
        for (int ks = 0; ks < 2; ks++) {
            uint32_t aF[2][4];
#pragma unroll
            for (int mt = 0; mt < 2; mt++) {
                int r = wm0 + mt * 16 + (lane & 15);
                int c = ch * 4 + ks * 2 + (lane >> 4);       // 16B chunk in h row
                ldsm4(aF[mt], hs + (uint32_t)(r * 512 + ((c ^ (r & 7)) << 4)));
            }
#pragma unroll
            for (int nt = 0; nt < 8; nt++) {
                int kk = ks * 16 + (lane & 15);
                int cc = (wn0 + nt * 8) >> 3;
                uint32_t bF[2];
                ldsm2t(bF, bb + (uint32_t)(kk * 512 + ((cc ^ (kk & 7)) << 4)));
#pragma unroll
                for (int mt = 0; mt < 2; mt++)
                    mma_f16(acc[mt][nt], aF[mt], bF);
            }
        }
        __syncthreads();
    }

    // phase B epilogue: cols 0-127 -> pf, cols 128-255 (+b2) -> qf
#pragma unroll
    for (int mt = 0; mt < 2; mt++) {
        int rl = wm0 + mt * 16 + (lane >> 2);
#pragma unroll
        for (int nt = 0; nt < 8; nt++) {
            int col = wn0 + nt * 8 + (lane & 3) * 2;
            float c0 = 0.f, c1 = 0.f;
            if (col >= 128) { c0 = b2[col - 128]; c1 = b2[col - 127]; }
#pragma unroll
            for (int half = 0; half < 2; half++) {
                int rr = row0 + rl + half * 8;
                if (rr >= NN) continue;
                float vx = acc[mt][nt][half * 2]     + c0;
                float vy = acc[mt][nt][half * 2 + 1] + c1;
                if (col < 128)
                    *(uint32_t*)(g_pf + (size_t)rr * 128 + col) = pkh(vx, vy);
                else
                    *(uint32_t*)(g_qf + (size_t)rr * 128 + (col - 128)) = pkh(vx, vy);
            }
        }
    }
}

// ---------------- layer-2 finish: refined = mean(p[srcs]) + q ----------------
__global__ void k_agg2f(float* __restrict__ refined) {
    int hw = threadIdx.x >> 4;
    int lane = threadIdx.x & 15;
    int node = blockIdx.x * 16 + hw;
    if (node >= NN) return;
    int beg = g_off[node], end = g_off[node + 1];
    float a[8];
#pragma unroll
    for (int i = 0; i < 8; i++) a[i] = 0.f;
    int e = beg;
    for (; e + 1 < end; e += 2) {
        int s0 = g_srcs[e], s1 = g_srcs[e + 1];
        uint4 v0 = ((const uint4*)(g_pf + (size_t)s0 * 128))[lane];
        uint4 v1 = ((const uint4*)(g_pf + (size_t)s1 * 128))[lane];
        acc8(a, v0);
        acc8(a, v1);
    }
    if (e < end) {
        uint4 v = ((const uint4*)(g_pf + (size_t)g_srcs[e] * 128))[lane];
        acc8(a, v);
    }
    int cnt = end - beg;
    float inv = 1.0f / (float)(cnt > 0 ? cnt : 1);
    uint4 qv = ((const uint4*)(g_qf + (size_t)node * 128))[lane];
    const uint32_t* qp = (const uint32_t*)&qv;
    float o[8];
#pragma unroll
    for (int i = 0; i < 4; i++) {
        float2 q2 = __half22float2(*(const __half2*)&qp[i]);
        o[2 * i]     = a[2 * i] * inv + q2.x;
        o[2 * i + 1] = a[2 * i + 1] * inv + q2.y;
    }
    float* rp = refined + (size_t)node * 128 + lane * 8;
    *(float4*)(rp)     = make_float4(o[0], o[1], o[2], o[3]);
    *(float4*)(rp + 4) = make_float4(o[4], o[5], o[6], o[7]);
    uint4 u;
    u.x = pkh(o[0], o[1]);
    u.y = pkh(o[2], o[3]);
    u.z = pkh(o[4], o[5]);
    u.w = pkh(o[6], o[7]);
    ((uint4*)(g_rf + (size_t)node * 128))[lane] = u;
}

// ---------------- CSR-order edge scoring (half-warp per dst, 2-edge MLP) -----
__global__ void k_score(float* __restrict__ out) {
    int hw = threadIdx.x >> 4;
    int lane = threadIdx.x & 15;
    int node = blockIdx.x * 16 + hw;
    if (node >= NN) return;
    int beg = g_off[node], end = g_off[node + 1];
    if (beg == end) return;
    uint4 va = ((const uint4*)(g_rf + (size_t)node * 128))[lane];
    const uint32_t* ap = (const uint32_t*)&va;
    float d[8];
#pragma unroll
    for (int i = 0; i < 4; i++) {
        float2 f = __half22float2(*(const __half2*)&ap[i]);
        d[2 * i] = f.x;
        d[2 * i + 1] = f.y;
    }
    int e = beg;
    for (; e + 1 < end; e += 2) {
        uint4 v0 = ((const uint4*)(g_rf + (size_t)g_srcs[e] * 128))[lane];
        uint4 v1 = ((const uint4*)(g_rf + (size_t)g_srcs[e + 1] * 128))[lane];
        const uint32_t* b0 = (const uint32_t*)&v0;
        const uint32_t* b1 = (const uint32_t*)&v1;
        float t0 = 0.f, t1 = 0.f;
#pragma unroll
        for (int i = 0; i < 4; i++) {
            float2 f0 = __half22float2(*(const __half2*)&b0[i]);
            float2 f1 = __half22float2(*(const __half2*)&b1[i]);
            t0 += d[2 * i] * f0.x + d[2 * i + 1] * f0.y;
            t1 += d[2 * i] * f1.x + d[2 * i + 1] * f1.y;
        }
#pragma unroll
        for (int o = 8; o > 0; o >>= 1) {
            t0 += __shfl_xor_sync(0xFFFFFFFFu, t0, o);
            t1 += __shfl_xor_sync(0xFFFFFFFFu, t1, o);
        }
        if (lane == 0) {
            out[g_eids[e]]     = t0;
            out[g_eids[e + 1]] = t1;
        }
    }
    if (e < end) {
        uint4 vb = ((const uint4*)(g_rf + (size_t)g_srcs[e] * 128))[lane];
        const uint32_t* bp = (const uint32_t*)&vb;
        float t = 0.f;
#pragma unroll
        for (int i = 0; i < 4; i++) {
            float2 f = __half22float2(*(const __half2*)&bp[i]);
            t += d[2 * i] * f.x + d[2 * i + 1] * f.y;
        }
#pragma unroll
        for (int o = 8; o > 0; o >>= 1) t += __shfl_xor_sync(0xFFFFFFFFu, t, o);
        if (lane == 0) out[g_eids[e]] = t;
    }
}

// ---------------- launch -----------------------------------------------------
extern "C" void kernel_launch(void* const* d_in, const int* in_sizes, int n_in,
                              void* d_out, int out_size)
{
    const void*  ei    = d_in[0];
    const float* movie = (const float*)d_in[2];
    const float* user  = (const float*)d_in[3];
    const float* Wl1   = (const float*)d_in[4];
    const float* bl1   = (const float*)d_in[5];
    const float* Wr1   = (const float*)d_in[6];
    const float* Wl2   = (const float*)d_in[7];
    const float* bl2   = (const float*)d_in[8];
    const float* Wr2   = (const float*)d_in[9];

    float* out     = (float*)d_out;
    float* refined = out + NE;

    const int MB = (NN + 127) / 128;      // 1172
    const int FSMEM = 118784;             // fused GEMM smem (1 CTA/SM)
    const int PREP_B = (NN * 128 / 8 + 255) / 256;   // 9375 (covers NE too)

    cudaFuncSetAttribute(k_gemm_fused, cudaFuncAttributeMaxDynamicSharedMemorySize, FSMEM);

    k_prep<<<PREP_B, 256>>>(ei, movie, user, Wl1, Wr1, Wl2, Wr2);
    k_scan1<<<(NN + 1023) / 1024, 1024>>>();
    k_scan2<<<1, 256>>>();
    k_scan3<<<(NN + 255) / 256, 256>>>();
    k_bucket<<<(NE + 255) / 256, 256>>>(ei);
    k_agg1<<<(NN + 15) / 16, 256>>>();
    k_gemm_fused<<<MB, 512, FSMEM>>>(bl1, bl2);
    k_agg2f<<<(NN + 15) / 16, 256>>>(refined);
    k_score<<<(NN + 15) / 16, 256>>>(out);
}

// round 17
// speedup vs baseline: 1.0142x; 1.0142x over previous
#include <cuda_runtime.h>
#include <cuda_bf16.h>
#include <cuda_fp16.h>
#include <cstdint>
#include <cstddef>

#define NM 100000           // movies
#define NU 50000            // users
#define NN 150000           // total nodes
#define NE 500000           // edges
#define D1 128              // emb dim
#define D2 256              // hidden dim

// ---------------- scratch (device globals; no allocation allowed) ----------
__device__ int g_deg[NN];          // zero-init at load; scan1 re-zeroes per run
__device__ int g_off[NN + 1];
__device__ int g_pos[NN];
__device__ int g_srcs[NE];
__device__ int g_eids[NE];
__device__ int g_bsum[256];
__device__ int g_is64;
// fp16 operands
__device__ __align__(256) __half g_xf[(size_t)NN * 128];     // embeddings fp16
__device__ __align__(256) __half g_a1f[(size_t)NN * 128];    // layer-1 aggregate
__device__ __align__(256) __half g_B1f[256 * 256];           // [Wl1;Wr1] k-major
__device__ __align__(256) __half g_B2f[256 * 256];           // [Wl2|Wr2] n-concat
__device__ __align__(256) __half g_pf[(size_t)NN * 128];     // p = h@Wl2 (fp16)
__device__ __align__(256) __half g_qf[(size_t)NN * 128];     // q = h@Wr2+b2 (fp16)
__device__ __align__(256) __half g_rf[(size_t)NN * 128];     // refined fp16 shadow

// ---------------- helpers ----------------------------------------------------
__device__ __forceinline__ int edge_idx(const void* ei, int which, int e) {
    if (g_is64) {
        const long long* p = (const long long*)ei;
        return (int)p[(size_t)which * NE + e];
    } else {
        const int* p = (const int*)ei;
        return p[(size_t)which * NE + e];
    }
}
__device__ __forceinline__ uint32_t pkh(float a, float b) {
    __half2 p = __floats2half2_rn(a, b);
    return *(uint32_t*)&p;
}
__device__ __forceinline__ void cpa16(uint32_t dst, const void* src) {
    asm volatile("cp.async.cg.shared.global [%0], [%1], 16;" :: "r"(dst), "l"(src));
}
__device__ __forceinline__ void cpa_commit() {
    asm volatile("cp.async.commit_group;" ::: "memory");
}
template <int N>
__device__ __forceinline__ void cpa_wait() {
    asm volatile("cp.async.wait_group %0;" :: "n"(N) : "memory");
}
__device__ __forceinline__ void ldsm4(uint32_t* r, uint32_t a) {
    asm volatile("ldmatrix.sync.aligned.m8n8.x4.shared.b16 {%0,%1,%2,%3}, [%4];"
                 : "=r"(r[0]), "=r"(r[1]), "=r"(r[2]), "=r"(r[3]) : "r"(a));
}
__device__ __forceinline__ void ldsm2t(uint32_t* r, uint32_t a) {
    asm volatile("ldmatrix.sync.aligned.m8n8.x2.trans.shared.b16 {%0,%1}, [%2];"
                 : "=r"(r[0]), "=r"(r[1]) : "r"(a));
}
__device__ __forceinline__ void mma_f16(float* c, const uint32_t* a, const uint32_t* b) {
    asm volatile(
        "mma.sync.aligned.m16n8k16.row.col.f32.f16.f16.f32 "
        "{%0,%1,%2,%3},{%4,%5,%6,%7},{%8,%9},{%0,%1,%2,%3};"
        : "+f"(c[0]), "+f"(c[1]), "+f"(c[2]), "+f"(c[3])
        : "r"(a[0]), "r"(a[1]), "r"(a[2]), "r"(a[3]), "r"(b[0]), "r"(b[1]));
}
__device__ __forceinline__ void acc8(float* a, uint4 v) {
    const uint32_t* vp = (const uint32_t*)&v;
#pragma unroll
    for (int i = 0; i < 4; i++) {
        float2 f = __half22float2(*(const __half2*)&vp[i]);
        a[2 * i]     += f.x;
        a[2 * i + 1] += f.y;
    }
}

// ---- fused prep: detect + degree count + split weights + split x ------------
__global__ void k_prep(const void* ei,
                       const float* __restrict__ movie, const float* __restrict__ user,
                       const float* __restrict__ Wl1, const float* __restrict__ Wr1,
                       const float* __restrict__ Wl2, const float* __restrict__ Wr2)
{
    int gid = blockIdx.x * 256 + threadIdx.x;
    if (blockIdx.x == 0) {
        const long long* p = (const long long*)ei;
        int bad = 0;
        for (int i = threadIdx.x; i < 2048; i += 256) {
            long long v = p[i];
            if (v < 0 || v >= NN) bad = 1;
        }
        bad = __syncthreads_or(bad);
        if (threadIdx.x == 0) g_is64 = bad ? 0 : 1;
    }
    // degree count (local is64 detection; first 32B broadcast from L1)
    if (gid < NE) {
        const long long* p64 = (const long long*)ei;
        long long a0 = p64[0], a1 = p64[1], a2 = p64[2], a3 = p64[3];
        bool is64 = (a0 >= 0 && a0 < NN) && (a1 >= 0 && a1 < NN) &&
                    (a2 >= 0 && a2 < NN) && (a3 >= 0 && a3 < NN);
        int d = is64 ? (int)p64[(size_t)NE + gid]
                     : ((const int*)ei)[(size_t)NE + gid];
        atomicAdd(&g_deg[d], 1);
    }
    if (gid < 65536) {                       // B1 [k=256][n=256] = [Wl1;Wr1]
        float v = (gid < 32768) ? Wl1[gid] : Wr1[gid - 32768];
        g_B1f[gid] = __float2half(v);
    } else if (gid < 131072) {               // B2 [k=256][n=256] = [Wl2|Wr2]
        int j = gid - 65536;
        int k = j >> 8, n = j & 255;
        float v = (n < 128) ? Wl2[(size_t)k * 128 + n]
                            : Wr2[(size_t)k * 128 + (n - 128)];
        g_B2f[j] = __float2half(v);
    }
    // x split: 8 floats -> 8 fp16 per thread (16B store)
    size_t i = (size_t)gid * 8;
    if (i < (size_t)NN * 128) {
        int row = (int)(i >> 7), col = (int)(i & 127);
        const float* src = (row < NM) ? movie + (size_t)row * 128 + col
                                      : user + (size_t)(row - NM) * 128 + col;
        float4 v0 = *(const float4*)src;
        float4 v1 = *(const float4*)(src + 4);
        uint4 u;
        u.x = pkh(v0.x, v0.y);
        u.y = pkh(v0.z, v0.w);
        u.z = pkh(v1.x, v1.y);
        u.w = pkh(v1.z, v1.w);
        *(uint4*)(g_xf + i) = u;
    }
}

// ---------------- CSR construction -------------------------------------------
// scan1: shuffle-based block scan; consumes g_deg and re-zeroes it.
__global__ void k_scan1() {
    __shared__ int wsum[32];
    int i = blockIdx.x * 1024 + threadIdx.x;
    int v = (i < NN) ? g_deg[i] : 0;
    if (i < NN) g_deg[i] = 0;                 // restore invariant for next run
    int lane = threadIdx.x & 31, w = threadIdx.x >> 5;
    int x = v;
#pragma unroll
    for (int o = 1; o < 32; o <<= 1) {
        int t = __shfl_up_sync(0xFFFFFFFFu, x, o);
        if (lane >= o) x += t;
    }
    if (lane == 31) wsum[w] = x;
    __syncthreads();
    if (w == 0) {
        int s = wsum[lane];
#pragma unroll
        for (int o = 1; o < 32; o <<= 1) {
            int t = __shfl_up_sync(0xFFFFFFFFu, s, o);
            if (lane >= o) s += t;
        }
        wsum[lane] = s;
    }
    __syncthreads();
    int incl = x + ((w > 0) ? wsum[w - 1] : 0);
    if (i < NN) g_off[i] = incl - v;          // exclusive
    if (threadIdx.x == 1023) g_bsum[blockIdx.x] = incl;
}

// scan23: each block redundantly computes the exclusive block-prefix of
// g_bsum (147 values, smem-local, no write-back) and applies it.
__global__ void k_scan23() {
    __shared__ int s[256];
    const int NB = (NN + 1023) / 1024;        // 147
    int t = threadIdx.x;
    int v = (t < NB) ? g_bsum[t] : 0;
    s[t] = v;
    __syncthreads();
#pragma unroll
    for (int off = 1; off < 256; off <<= 1) {
        int u = (t >= off) ? s[t - off] : 0;
        __syncthreads();
        s[t] += u;
        __syncthreads();
    }
    s[t] -= v;                                // exclusive prefix
    __syncthreads();
    int i = blockIdx.x * 256 + t;
    if (i < NN) {
        int val = g_off[i] + s[i >> 10];
        g_off[i] = val;
        g_pos[i] = val;
    }
    if (i == 0) g_off[NN] = NE;
}

__global__ void k_bucket(const void* ei) {
    int e = blockIdx.x * blockDim.x + threadIdx.x;
    if (e < NE) {
        int d = edge_idx(ei, 1, e);
        int p = atomicAdd(&g_pos[d], 1);
        g_srcs[p] = edge_idx(ei, 0, e);
        g_eids[p] = e;
    }
}

// ---------------- layer-1 aggregation (half-warp per node, MLP=2) -----------
__global__ void k_agg1() {
    int hw = threadIdx.x >> 4;
    int lane = threadIdx.x & 15;
    int node = blockIdx.x * 16 + hw;
    if (node >= NN) return;
    int beg = g_off[node], end = g_off[node + 1];
    float a[8];
#pragma unroll
    for (int i = 0; i < 8; i++) a[i] = 0.f;
    int e = beg;
    for (; e + 1 < end; e += 2) {
        int s0 = g_srcs[e], s1 = g_srcs[e + 1];
        uint4 v0 = ((const uint4*)(g_xf + (size_t)s0 * 128))[lane];
        uint4 v1 = ((const uint4*)(g_xf + (size_t)s1 * 128))[lane];
        acc8(a, v0);
        acc8(a, v1);
    }
    if (e < end) {
        uint4 v = ((const uint4*)(g_xf + (size_t)g_srcs[e] * 128))[lane];
        acc8(a, v);
    }
    int cnt = end - beg;
    float inv = 1.0f / (float)(cnt > 0 ? cnt : 1);
    uint4 u;
    u.x = pkh(a[0] * inv, a[1] * inv);
    u.y = pkh(a[2] * inv, a[3] * inv);
    u.z = pkh(a[4] * inv, a[5] * inv);
    u.w = pkh(a[6] * inv, a[7] * inv);
    ((uint4*)(g_a1f + (size_t)node * 128))[lane] = u;
}

// ---------------- fused dual GEMM (BM=128, 512 thr, 1 CTA/SM) ----------------
// Phase A: h = relu([a1|x]@B1 + b1)   -> h tile in smem (swizzled, 64KB)
// Phase B: [p|q] = h@B2 (+b2 on q)    -> g_pf, g_qf fp16
// 16 warps (4m x 4n), warp tile 32x64, BK=32 double-buffered.
// smem: [0,20480) A stages | [20480,53248) B stages | [53248,118784) h
__global__ void __launch_bounds__(512, 1) k_gemm_fused(
    const float* __restrict__ b1, const float* __restrict__ b2)
{
    constexpr int ASTG = 10240;          // 128 rows x 80B
    constexpr int BSTG = 16384;          // 32 rows x 512B
    constexpr uint32_t BOFF = 20480;
    constexpr uint32_t HOFF = 53248;

    extern __shared__ char smr[];
    uint32_t sm0 = (uint32_t)__cvta_generic_to_shared(smr);
    uint32_t hs  = sm0 + HOFF;

    int tid = threadIdx.x, lane = tid & 31, warp = tid >> 5;
    int wm0 = (warp >> 2) * 32, wn0 = (warp & 3) * 64;
    int row0 = blockIdx.x * 128;

    float acc[2][8][4];
#pragma unroll
    for (int i = 0; i < 2; i++)
#pragma unroll
        for (int j = 0; j < 8; j++)
#pragma unroll
            for (int q = 0; q < 4; q++) acc[i][j][q] = 0.f;

    // ---------------- phase A ----------------
    auto stageA = [&](int ch, int s) {
        {
            int row = tid >> 2, c = tid & 3;
            int grow = row0 + row;
            if (grow >= NN) grow = 0;
            int kk = ch * 32 + c * 8;
            const __half* src = (kk < 128)
                ? g_a1f + (size_t)grow * 128 + kk
                : g_xf  + (size_t)grow * 128 + (kk - 128);
            cpa16(sm0 + (uint32_t)(s * ASTG + row * 80 + c * 16), src);
        }
#pragma unroll
        for (int i = 0; i < 2; i++) {
            int idx = tid + i * 512;
            int k = idx >> 5, c = idx & 31;
            const __half* src = g_B1f + (size_t)(ch * 32 + k) * 256 + c * 8;
            cpa16(sm0 + BOFF + (uint32_t)(s * BSTG + k * 512 + ((c ^ (k & 7)) << 4)), src);
        }
    };

    stageA(0, 0);
    cpa_commit();
    for (int ch = 0; ch < 8; ch++) {
        int s = ch & 1;
        if (ch + 1 < 8) {
            stageA(ch + 1, (ch + 1) & 1);
            cpa_commit();
            cpa_wait<1>();
        } else {
            cpa_wait<0>();
        }
        __syncthreads();
        uint32_t ab = sm0 + (uint32_t)(s * ASTG);
        uint32_t bb = sm0 + BOFF + (uint32_t)(s * BSTG);
#pragma unroll
        for (int ks = 0; ks < 2; ks++) {
            uint32_t aF[2][4];
#pragma unroll
            for (int mt = 0; mt < 2; mt++) {
                int r  = wm0 + mt * 16 + (lane & 15);
                int kc = ks * 16 + ((lane >> 4) << 3);
                ldsm4(aF[mt], ab + (uint32_t)(r * 80 + kc * 2));
            }
#pragma unroll
            for (int nt = 0; nt < 8; nt++) {
                int kk = ks * 16 + (lane & 15);
                int cc = (wn0 + nt * 8) >> 3;
                uint32_t bF[2];
                ldsm2t(bF, bb + (uint32_t)(kk * 512 + ((cc ^ (kk & 7)) << 4)));
#pragma unroll
                for (int mt = 0; mt < 2; mt++)
                    mma_f16(acc[mt][nt], aF[mt], bF);
            }
        }
        __syncthreads();
    }

    // phase A epilogue: bias + relu -> h smem (swizzled, 512B row stride)
#pragma unroll
    for (int mt = 0; mt < 2; mt++) {
        int rl = wm0 + mt * 16 + (lane >> 2);
#pragma unroll
        for (int nt = 0; nt < 8; nt++) {
            int col = wn0 + nt * 8 + (lane & 3) * 2;
            float c0 = b1[col], c1 = b1[col + 1];
#pragma unroll
            for (int half = 0; half < 2; half++) {
                int rr = rl + half * 8;
                float vx = fmaxf(acc[mt][nt][half * 2]     + c0, 0.f);
                float vy = fmaxf(acc[mt][nt][half * 2 + 1] + c1, 0.f);
                uint32_t addr = hs + (uint32_t)(rr * 512 +
                    (((col >> 3) ^ (rr & 7)) << 4) + (col & 7) * 2);
                asm volatile("st.shared.b32 [%0], %1;" :: "r"(addr), "r"(pkh(vx, vy)) : "memory");
            }
        }
    }
#pragma unroll
    for (int i = 0; i < 2; i++)
#pragma unroll
        for (int j = 0; j < 8; j++)
#pragma unroll
            for (int q = 0; q < 4; q++) acc[i][j][q] = 0.f;
    __syncthreads();

    // ---------------- phase B: [p|q] = h @ B2 ----------------
    auto stageB = [&](int ch, int s) {
#pragma unroll
        for (int i = 0; i < 2; i++) {
            int idx = tid + i * 512;
            int k = idx >> 5, c = idx & 31;
            const __half* src = g_B2f + (size_t)(ch * 32 + k) * 256 + c * 8;
            cpa16(sm0 + BOFF + (uint32_t)(s * BSTG + k * 512 + ((c ^ (k & 7)) << 4)), src);
        }
    };

    stageB(0, 0);
    cpa_commit();
    for (int ch = 0; ch < 8; ch++) {
        int s = ch & 1;
        if (ch + 1 < 8) {
            stageB(ch + 1, (ch + 1) & 1);
            cpa_commit();
            cpa_wait<1>();
        } else {
            cpa_wait<0>();
        }
        __syncthreads();
        uint32_t bb = sm0 + BOFF + (uint32_t)(s * BSTG);
#pragma unroll
        for (int ks = 0; ks < 2; ks++) {
            uint32_t aF[2][4];
#pragma unroll
            for (int mt = 0; mt < 2; mt++) {
                int r = wm0 + mt * 16 + (lane & 15);
                int c = ch * 4 + ks * 2 + (lane >> 4);       // 16B chunk in h row
                ldsm4(aF[mt], hs + (uint32_t)(r * 512 + ((c ^ (r & 7)) << 4)));
            }
#pragma unroll
            for (int nt = 0; nt < 8; nt++) {
                int kk = ks * 16 + (lane & 15);
                int cc = (wn0 + nt * 8) >> 3;
                uint32_t bF[2];
                ldsm2t(bF, bb + (uint32_t)(kk * 512 + ((cc ^ (kk & 7)) << 4)));
#pragma unroll
                for (int mt = 0; mt < 2; mt++)
                    mma_f16(acc[mt][nt], aF[mt], bF);
            }
        }
        __syncthreads();
    }

    // phase B epilogue: cols 0-127 -> pf, cols 128-255 (+b2) -> qf
#pragma unroll
    for (int mt = 0; mt < 2; mt++) {
        int rl = wm0 + mt * 16 + (lane >> 2);
#pragma unroll
        for (int nt = 0; nt < 8; nt++) {
            int col = wn0 + nt * 8 + (lane & 3) * 2;
            float c0 = 0.f, c1 = 0.f;
            if (col >= 128) { c0 = b2[col - 128]; c1 = b2[col - 127]; }
#pragma unroll
            for (int half = 0; half < 2; half++) {
                int rr = row0 + rl + half * 8;
                if (rr >= NN) continue;
                float vx = acc[mt][nt][half * 2]     + c0;
                float vy = acc[mt][nt][half * 2 + 1] + c1;
                if (col < 128)
                    *(uint32_t*)(g_pf + (size_t)rr * 128 + col) = pkh(vx, vy);
                else
                    *(uint32_t*)(g_qf + (size_t)rr * 128 + (col - 128)) = pkh(vx, vy);
            }
        }
    }
}

// ---------------- layer-2 finish: refined = mean(p[srcs]) + q ----------------
__global__ void k_agg2f(float* __restrict__ refined) {
    int hw = threadIdx.x >> 4;
    int lane = threadIdx.x & 15;
    int node = blockIdx.x * 16 + hw;
    if (node >= NN) return;
    int beg = g_off[node], end = g_off[node + 1];
    float a[8];
#pragma unroll
    for (int i = 0; i < 8; i++) a[i] = 0.f;
    int e = beg;
    for (; e + 1 < end; e += 2) {
        int s0 = g_srcs[e], s1 = g_srcs[e + 1];
        uint4 v0 = ((const uint4*)(g_pf + (size_t)s0 * 128))[lane];
        uint4 v1 = ((const uint4*)(g_pf + (size_t)s1 * 128))[lane];
        acc8(a, v0);
        acc8(a, v1);
    }
    if (e < end) {
        uint4 v = ((const uint4*)(g_pf + (size_t)g_srcs[e] * 128))[lane];
        acc8(a, v);
    }
    int cnt = end - beg;
    float inv = 1.0f / (float)(cnt > 0 ? cnt : 1);
    uint4 qv = ((const uint4*)(g_qf + (size_t)node * 128))[lane];
    const uint32_t* qp = (const uint32_t*)&qv;
    float o[8];
#pragma unroll
    for (int i = 0; i < 4; i++) {
        float2 q2 = __half22float2(*(const __half2*)&qp[i]);
        o[2 * i]     = a[2 * i] * inv + q2.x;
        o[2 * i + 1] = a[2 * i + 1] * inv + q2.y;
    }
    float* rp = refined + (size_t)node * 128 + lane * 8;
    *(float4*)(rp)     = make_float4(o[0], o[1], o[2], o[3]);
    *(float4*)(rp + 4) = make_float4(o[4], o[5], o[6], o[7]);
    uint4 u;
    u.x = pkh(o[0], o[1]);
    u.y = pkh(o[2], o[3]);
    u.z = pkh(o[4], o[5]);
    u.w = pkh(o[6], o[7]);
    ((uint4*)(g_rf + (size_t)node * 128))[lane] = u;
}

// ---------------- CSR-order edge scoring (half-warp per dst, 2-edge MLP) -----
__global__ void k_score(float* __restrict__ out) {
    int hw = threadIdx.x >> 4;
    int lane = threadIdx.x & 15;
    int node = blockIdx.x * 16 + hw;
    if (node >= NN) return;
    int beg = g_off[node], end = g_off[node + 1];
    if (beg == end) return;
    uint4 va = ((const uint4*)(g_rf + (size_t)node * 128))[lane];
    const uint32_t* ap = (const uint32_t*)&va;
    float d[8];
#pragma unroll
    for (int i = 0; i < 4; i++) {
        float2 f = __half22float2(*(const __half2*)&ap[i]);
        d[2 * i] = f.x;
        d[2 * i + 1] = f.y;
    }
    int e = beg;
    for (; e + 1 < end; e += 2) {
        uint4 v0 = ((const uint4*)(g_rf + (size_t)g_srcs[e] * 128))[lane];
        uint4 v1 = ((const uint4*)(g_rf + (size_t)g_srcs[e + 1] * 128))[lane];
        const uint32_t* b0 = (const uint32_t*)&v0;
        const uint32_t* b1 = (const uint32_t*)&v1;
        float t0 = 0.f, t1 = 0.f;
#pragma unroll
        for (int i = 0; i < 4; i++) {
            float2 f0 = __half22float2(*(const __half2*)&b0[i]);
            float2 f1 = __half22float2(*(const __half2*)&b1[i]);
            t0 += d[2 * i] * f0.x + d[2 * i + 1] * f0.y;
            t1 += d[2 * i] * f1.x + d[2 * i + 1] * f1.y;
        }
#pragma unroll
        for (int o = 8; o > 0; o >>= 1) {
            t0 += __shfl_xor_sync(0xFFFFFFFFu, t0, o);
            t1 += __shfl_xor_sync(0xFFFFFFFFu, t1, o);
        }
        if (lane == 0) {
            out[g_eids[e]]     = t0;
            out[g_eids[e + 1]] = t1;
        }
    }
    if (e < end) {
        uint4 vb = ((const uint4*)(g_rf + (size_t)g_srcs[e] * 128))[lane];
        const uint32_t* bp = (const uint32_t*)&vb;
        float t = 0.f;
#pragma unroll
        for (int i = 0; i < 4; i++) {
            float2 f = __half22float2(*(const __half2*)&bp[i]);
            t += d[2 * i] * f.x + d[2 * i + 1] * f.y;
        }
#pragma unroll
        for (int o = 8; o > 0; o >>= 1) t += __shfl_xor_sync(0xFFFFFFFFu, t, o);
        if (lane == 0) out[g_eids[e]] = t;
    }
}

// ---------------- launch -----------------------------------------------------
extern "C" void kernel_launch(void* const* d_in, const int* in_sizes, int n_in,
                              void* d_out, int out_size)
{
    const void*  ei    = d_in[0];
    const float* movie = (const float*)d_in[2];
    const float* user  = (const float*)d_in[3];
    const float* Wl1   = (const float*)d_in[4];
    const float* bl1   = (const float*)d_in[5];
    const float* Wr1   = (const float*)d_in[6];
    const float* Wl2   = (const float*)d_in[7];
    const float* bl2   = (const float*)d_in[8];
    const float* Wr2   = (const float*)d_in[9];

    float* out     = (float*)d_out;
    float* refined = out + NE;

    const int MB = (NN + 127) / 128;      // 1172
    const int FSMEM = 118784;             // fused GEMM smem (1 CTA/SM)
    const int PREP_B = (NN * 128 / 8 + 255) / 256;   // 9375 (covers NE too)

    cudaFuncSetAttribute(k_gemm_fused, cudaFuncAttributeMaxDynamicSharedMemorySize, FSMEM);

    k_prep<<<PREP_B, 256>>>(ei, movie, user, Wl1, Wr1, Wl2, Wr2);
    k_scan1<<<(NN + 1023) / 1024, 1024>>>();
    k_scan23<<<(NN + 255) / 256, 256>>>();
    k_bucket<<<(NE + 255) / 256, 256>>>(ei);
    k_agg1<<<(NN + 15) / 16, 256>>>();
    k_gemm_fused<<<MB, 512, FSMEM>>>(bl1, bl2);
    k_agg2f<<<(NN + 15) / 16, 256>>>(refined);
    k_score<<<(NN + 15) / 16, 256>>>(out);
}